// round 12
// baseline (speedup 1.0000x reference)
#include <cuda_runtime.h>
#include <cuda_fp16.h>
#include <mma.h>
#include <cstdint>

using namespace nvcuda;

#define NN 50000
#define NE 800000
#define CAP 96   // max in-degree bucket capacity (Poisson(16): P(deg>=96) ~ 1e-40)

// ---------------- scratch (static device allocations; no cudaMalloc) ----------------
__device__ int   g_cnt[NN];
__device__ int   g_fill[NN];
__device__ __align__(16) int g_colsrc[(size_t)NN * CAP];
__device__ float g_dinv[NN];
__device__ __align__(16) __half g_x16[(size_t)NN * 128];        // fp16 copy of x
__device__ __align__(16) __half g_w16[128 * 128 + 128 * 64 + 64 * 64];  // fp16 W1|W2|W3
__device__ __align__(16) __half g_u[(size_t)NN * 128];  // pre-agg messages, PRESCALED by dinv[src]
__device__ __align__(16) __half g_h[(size_t)NN * 128];  // post-agg activations (fp16)

// ---------------- helpers ----------------
__device__ __forceinline__ uint32_t smem_u32(const void* p) {
    uint32_t a;
    asm("{ .reg .u64 t; cvta.to.shared.u64 t, %1; cvt.u32.u64 %0, t; }" : "=r"(a) : "l"(p));
    return a;
}
__device__ __forceinline__ void cpa16(uint32_t dst, const void* src, int srcsz) {
    asm volatile("cp.async.ca.shared.global [%0], [%1], 16, %2;"
                 :: "r"(dst), "l"(src), "r"(srcsz));
}
#define CP_COMMIT() asm volatile("cp.async.commit_group;")
#define CP_WAIT(n)  asm volatile("cp.async.wait_group %0;" :: "n"(n))

// ---------------- conversion kernels ----------------
__global__ void k_xconv(const float* __restrict__ x) {
    int i = blockIdx.x * blockDim.x + threadIdx.x;  // one uint4 out = 8 halves
    if (i < NN * 16) {
        const float4* src = (const float4*)x + i * 2;
        float4 v0 = src[0], v1 = src[1];
        __half2 h0 = __floats2half2_rn(v0.x, v0.y), h1 = __floats2half2_rn(v0.z, v0.w);
        __half2 h2 = __floats2half2_rn(v1.x, v1.y), h3 = __floats2half2_rn(v1.z, v1.w);
        ((uint4*)g_x16)[i] =
            make_uint4(*(uint32_t*)&h0, *(uint32_t*)&h1, *(uint32_t*)&h2, *(uint32_t*)&h3);
    }
}

__global__ void k_wconv(const float* __restrict__ W1, const float* __restrict__ W2,
                        const float* __restrict__ W3) {
    int i = blockIdx.x * blockDim.x + threadIdx.x;
    const int N1 = 128 * 128, N2 = 128 * 64, N3 = 64 * 64;
    if (i < N1) g_w16[i] = __float2half_rn(W1[i]);
    else if (i < N1 + N2) g_w16[i] = __float2half_rn(W2[i - N1]);
    else if (i < N1 + N2 + N3) g_w16[i] = __float2half_rn(W3[i - N1 - N2]);
}

// ---------------- bucket build ----------------
__global__ void k_count(const int* __restrict__ ei) {
    int e = blockIdx.x * blockDim.x + threadIdx.x;
    if (e < NE) atomicAdd(&g_cnt[ei[NE + e]], 1);
}

__global__ void k_dinv() {
    int i = blockIdx.x * blockDim.x + threadIdx.x;
    if (i < NN) g_dinv[i] = rsqrtf((float)(g_cnt[i] + 1));  // +1 self loop
}

__global__ void k_place(const int* __restrict__ ei) {
    int e = blockIdx.x * blockDim.x + threadIdx.x;
    if (e < NE) {
        int s = ei[e];
        int d = ei[NE + e];
        int pos = atomicAdd(&g_fill[d], 1);
        if (pos < CAP) g_colsrc[(size_t)d * CAP + pos] = s;
    }
}

// ---------------- cp.async double-buffered fp16 GEMM ----------------
// U[128-tile, FOUT] = (A @ Wh) * (SCALE ? dinv[row] : 1); fp16 in, fp32 accum, fp16 out.
template <int FIN, int FOUT, bool SCALE>
__global__ void __launch_bounds__(256, 2) k_gemm(const __half* __restrict__ A,
                                                 const __half* __restrict__ Wh) {
    __shared__ __align__(16) __half As[2][128][40];
    __shared__ __align__(16) __half Bs[2][32][FOUT + 8];
    __shared__ __align__(16) float  Cs[8][16][20];

    constexpr int NBI = FOUT / 64;  // B chunks per thread per stage

    int tid = threadIdx.x, wid = tid >> 5, lane = tid & 31;
    int row0 = blockIdx.x * 128;

    int ar = tid >> 1, ac0 = (tid & 1) * 16;
    int asz = (row0 + ar < NN) ? 16 : 0;  // zfill OOB rows
    const __half* arow = A + (size_t)(row0 + ar) * FIN + ac0;

    auto loadStage = [&](int k0, int st) {
        uint32_t ad = smem_u32(&As[st][ar][ac0]);
        cpa16(ad,      arow + k0,     asz);
        cpa16(ad + 16, arow + k0 + 8, asz);
        #pragma unroll
        for (int it = 0; it < NBI; it++) {
            int chunk = tid + it * 256;
            int k = chunk / (FOUT / 8);
            int n8 = (chunk % (FOUT / 8)) * 8;
            cpa16(smem_u32(&Bs[st][k][n8]), Wh + (size_t)(k0 + k) * FOUT + n8, 16);
        }
    };

    wmma::fragment<wmma::accumulator, 16, 16, 16, float> acc[FOUT / 16];
    #pragma unroll
    for (int j = 0; j < FOUT / 16; j++) wmma::fill_fragment(acc[j], 0.0f);

    loadStage(0, 0);
    CP_COMMIT();

    int st = 0;
    #pragma unroll
    for (int k0 = 0; k0 < FIN; k0 += 32, st ^= 1) {
        if (k0 + 32 < FIN) {
            loadStage(k0 + 32, st ^ 1);
            CP_COMMIT();
            CP_WAIT(1);
        } else {
            CP_WAIT(0);
        }
        __syncthreads();
        #pragma unroll
        for (int kk = 0; kk < 32; kk += 16) {
            wmma::fragment<wmma::matrix_a, 16, 16, 16, __half, wmma::row_major> af;
            wmma::load_matrix_sync(af, &As[st][wid * 16][kk], 40);
            #pragma unroll
            for (int j = 0; j < FOUT / 16; j++) {
                wmma::fragment<wmma::matrix_b, 16, 16, 16, __half, wmma::row_major> bf;
                wmma::load_matrix_sync(bf, &Bs[st][kk][j * 16], FOUT + 8);
                wmma::mma_sync(acc[j], af, bf, acc[j]);
            }
        }
        __syncthreads();  // stage st fully consumed before it is reloaded
    }

    #pragma unroll
    for (int j = 0; j < FOUT / 16; j++) {
        wmma::store_matrix_sync(&Cs[wid][0][0], acc[j], 20, wmma::mem_row_major);
        __syncwarp();
        int r = lane >> 1, c0 = (lane & 1) * 8;
        int grr = row0 + wid * 16 + r;
        if (grr < NN) {
            float dd = SCALE ? g_dinv[grr] : 1.0f;
            const float* s = &Cs[wid][r][c0];
            __half2 h0 = __floats2half2_rn(s[0] * dd, s[1] * dd);
            __half2 h1 = __floats2half2_rn(s[2] * dd, s[3] * dd);
            __half2 h2 = __floats2half2_rn(s[4] * dd, s[5] * dd);
            __half2 h3 = __floats2half2_rn(s[6] * dd, s[7] * dd);
            *(uint4*)(g_u + (size_t)grr * FOUT + j * 16 + c0) =
                make_uint4(*(uint32_t*)&h0, *(uint32_t*)&h1, *(uint32_t*)&h2, *(uint32_t*)&h3);
        }
        __syncwarp();
    }
}

// ---------------- bucket gather aggregation: half2 accumulate, fp32 finish ----------------
__global__ void k_agg128(const float* __restrict__ bias) {
    int w = (blockIdx.x * blockDim.x + threadIdx.x) >> 5;
    int lane = threadIdx.x & 31;
    if (w >= NN) return;
    const uint2* Uv = (const uint2*)g_u;
    uint2 sv = Uv[(w << 5) + lane];
    __half2 a0 = *(__half2*)&sv.x, a1 = *(__half2*)&sv.y;
    int deg = g_cnt[w]; if (deg > CAP) deg = CAP;
    const int4* row4 = (const int4*)(g_colsrc + w * CAP);
    int e = 0;
    for (; e + 4 <= deg; e += 4) {
        int4 s = row4[e >> 2];
        uint2 v0 = Uv[(s.x << 5) + lane];
        uint2 v1 = Uv[(s.y << 5) + lane];
        uint2 v2 = Uv[(s.z << 5) + lane];
        uint2 v3 = Uv[(s.w << 5) + lane];
        a0 = __hadd2(a0, *(__half2*)&v0.x); a1 = __hadd2(a1, *(__half2*)&v0.y);
        a0 = __hadd2(a0, *(__half2*)&v1.x); a1 = __hadd2(a1, *(__half2*)&v1.y);
        a0 = __hadd2(a0, *(__half2*)&v2.x); a1 = __hadd2(a1, *(__half2*)&v2.y);
        a0 = __hadd2(a0, *(__half2*)&v3.x); a1 = __hadd2(a1, *(__half2*)&v3.y);
    }
    for (; e < deg; e++) {
        int s = g_colsrc[w * CAP + e];
        uint2 v = Uv[(s << 5) + lane];
        a0 = __hadd2(a0, *(__half2*)&v.x); a1 = __hadd2(a1, *(__half2*)&v.y);
    }
    float dd = g_dinv[w];
    float2 f0 = __half22float2(a0), f1 = __half22float2(a1);
    float4 bb = ((const float4*)bias)[lane];
    __half2 o0 = __floats2half2_rn(fmaxf(fmaf(f0.x, dd, bb.x), 0.f),
                                   fmaxf(fmaf(f0.y, dd, bb.y), 0.f));
    __half2 o1 = __floats2half2_rn(fmaxf(fmaf(f1.x, dd, bb.z), 0.f),
                                   fmaxf(fmaf(f1.y, dd, bb.w), 0.f));
    ((uint2*)g_h)[(w << 5) + lane] = make_uint2(*(uint32_t*)&o0, *(uint32_t*)&o1);
}

__global__ void k_agg64(const float* __restrict__ bias) {
    int w = (blockIdx.x * blockDim.x + threadIdx.x) >> 5;
    int lane = threadIdx.x & 31;
    if (w >= NN) return;
    const uint32_t* Uv = (const uint32_t*)g_u;
    uint32_t sv = Uv[(w << 5) + lane];
    __half2 a0 = *(__half2*)&sv;
    int deg = g_cnt[w]; if (deg > CAP) deg = CAP;
    const int4* row4 = (const int4*)(g_colsrc + w * CAP);
    int e = 0;
    for (; e + 4 <= deg; e += 4) {
        int4 s = row4[e >> 2];
        uint32_t v0 = Uv[(s.x << 5) + lane];
        uint32_t v1 = Uv[(s.y << 5) + lane];
        uint32_t v2 = Uv[(s.z << 5) + lane];
        uint32_t v3 = Uv[(s.w << 5) + lane];
        a0 = __hadd2(a0, *(__half2*)&v0);
        a0 = __hadd2(a0, *(__half2*)&v1);
        a0 = __hadd2(a0, *(__half2*)&v2);
        a0 = __hadd2(a0, *(__half2*)&v3);
    }
    for (; e < deg; e++) {
        int s = g_colsrc[w * CAP + e];
        uint32_t v = Uv[(s << 5) + lane];
        a0 = __hadd2(a0, *(__half2*)&v);
    }
    float dd = g_dinv[w];
    float2 f = __half22float2(a0);
    float2 bb = ((const float2*)bias)[lane];
    __half2 o = __floats2half2_rn(fmaxf(fmaf(f.x, dd, bb.x), 0.f),
                                  fmaxf(fmaf(f.y, dd, bb.y), 0.f));
    ((uint32_t*)g_h)[(w << 5) + lane] = *(uint32_t*)&o;
}

// ---------------- prototype-distance head + MLP + y copy ----------------
__device__ __forceinline__ float gelu_exact(float x) {
    return 0.5f * x * (1.0f + erff(x * 0.70710678118654752f));
}

__global__ void k_head(const float* __restrict__ prot,
                       const float* __restrict__ Wf0, const float* __restrict__ bf0,
                       const float* __restrict__ Wf1, const float* __restrict__ bf1,
                       const int* __restrict__ y,
                       float* __restrict__ out, int out_size) {
    __shared__ float hs[128][65];
    __shared__ float ps[16][64];
    __shared__ float pn[16];
    __shared__ float w0[16][8];
    __shared__ float b0[8];
    __shared__ float w1[8];
    __shared__ float b1s;

    int t = threadIdx.x;
    int nd0 = blockIdx.x * 128;

    for (int idx = t; idx < 128 * 64; idx += 128) {
        int r = idx >> 6, c = idx & 63;
        int node = nd0 + r;
        hs[r][c] = (node < NN) ? __half2float(g_h[(size_t)node * 64 + c]) : 0.f;
    }
    for (int idx = t; idx < 16 * 64; idx += 128)
        ps[idx >> 6][idx & 63] = prot[idx];
    if (t < 16 * 8) w0[t >> 3][t & 7] = Wf0[t];
    if (t < 8) { b0[t] = bf0[t]; w1[t] = Wf1[t]; }
    if (t == 0) b1s = bf1[0];
    __syncthreads();
    if (t < 16) {
        float s = 0.f;
        #pragma unroll
        for (int c = 0; c < 64; c++) s += ps[t][c] * ps[t][c];
        pn[t] = s;
    }
    __syncthreads();

    int node = nd0 + t;
    if (node < NN) {
        float hh = 0.f;
        #pragma unroll
        for (int c = 0; c < 64; c++) hh = fmaf(hs[t][c], hs[t][c], hh);

        float sim[16];
        #pragma unroll
        for (int k = 0; k < 16; k++) {
            float dot = 0.f;
            #pragma unroll
            for (int c = 0; c < 64; c++) dot = fmaf(hs[t][c], ps[k][c], dot);
            float d2 = fmaxf(hh + pn[k] - 2.0f * dot, 0.f);
            sim[k] = logf((d2 + 1.0f) / (d2 + 1e-4f));
        }

        float o = b1s;
        #pragma unroll
        for (int j = 0; j < 8; j++) {
            float z = b0[j];
            #pragma unroll
            for (int k = 0; k < 16; k++) z = fmaf(sim[k], w0[k][j], z);
            o = fmaf(gelu_exact(z), w1[j], o);
        }
        out[node] = 1.0f / (1.0f + expf(-o));
        if (NN + node < out_size) out[NN + node] = (float)y[node];
    }
}

// ---------------- launch ----------------
extern "C" void kernel_launch(void* const* d_in, const int* in_sizes, int n_in,
                              void* d_out, int out_size) {
    const float* x    = (const float*)d_in[0];
    const int*   ei   = (const int*)d_in[1];
    const int*   y    = (const int*)d_in[2];
    const float* W1   = (const float*)d_in[3];
    const float* b1   = (const float*)d_in[4];
    const float* W2   = (const float*)d_in[5];
    const float* b2   = (const float*)d_in[6];
    const float* W3   = (const float*)d_in[7];
    const float* b3   = (const float*)d_in[8];
    const float* prot = (const float*)d_in[9];
    const float* Wf0  = (const float*)d_in[10];
    const float* bf0  = (const float*)d_in[11];
    const float* Wf1  = (const float*)d_in[12];
    const float* bf1  = (const float*)d_in[13];
    float* out = (float*)d_out;

    static cudaStream_t s2 = nullptr;
    static cudaEvent_t evFork = nullptr, evDinv = nullptr, evJoin = nullptr;
    static void* cntPtr = nullptr;
    static void* fillPtr = nullptr;
    static __half* x16Ptr = nullptr;
    static __half* w16Ptr = nullptr;
    static __half* hPtr = nullptr;
    if (!s2) {
        cudaStreamCreateWithFlags(&s2, cudaStreamNonBlocking);
        cudaEventCreateWithFlags(&evFork, cudaEventDisableTiming);
        cudaEventCreateWithFlags(&evDinv, cudaEventDisableTiming);
        cudaEventCreateWithFlags(&evJoin, cudaEventDisableTiming);
        cudaGetSymbolAddress(&cntPtr, g_cnt);
        cudaGetSymbolAddress(&fillPtr, g_fill);
        void* p;
        cudaGetSymbolAddress(&p, g_x16); x16Ptr = (__half*)p;
        cudaGetSymbolAddress(&p, g_w16); w16Ptr = (__half*)p;
        cudaGetSymbolAddress(&p, g_h);   hPtr = (__half*)p;
    }

    const int MT = (NN + 127) / 128;  // 391 M-tiles
    int aggBlocks = (NN * 32 + 255) / 256;

    // fork: s2 does W conversion + bucket build
    cudaEventRecord(evFork, 0);
    cudaStreamWaitEvent(s2, evFork, 0);
    k_wconv<<<(128 * 128 + 128 * 64 + 64 * 64 + 255) / 256, 256, 0, s2>>>(W1, W2, W3);
    cudaMemsetAsync(cntPtr, 0, sizeof(int) * NN, s2);
    cudaMemsetAsync(fillPtr, 0, sizeof(int) * NN, s2);
    k_count<<<(NE + 255) / 256, 256, 0, s2>>>(ei);
    k_dinv<<<(NN + 255) / 256, 256, 0, s2>>>();
    cudaEventRecord(evDinv, s2);
    k_place<<<(NE + 255) / 256, 256, 0, s2>>>(ei);
    cudaEventRecord(evJoin, s2);

    // main: x conversion, then scaled GEMM1 (needs dinv + w16)
    k_xconv<<<(NN * 16 + 255) / 256, 256>>>(x);
    cudaStreamWaitEvent(0, evDinv, 0);  // dinv + w16 ready
    k_gemm<128, 128, true><<<MT, 256>>>(x16Ptr, w16Ptr);

    cudaStreamWaitEvent(0, evJoin, 0);  // buckets ready

    k_agg128<<<aggBlocks, 256>>>(b1);
    k_gemm<128, 64, true><<<MT, 256>>>(hPtr, w16Ptr + 128 * 128);
    k_agg64<<<aggBlocks, 256>>>(b2);
    k_gemm<64, 64, true><<<MT, 256>>>(hPtr, w16Ptr + 128 * 128 + 128 * 64);
    k_agg64<<<aggBlocks, 256>>>(b3);
    k_head<<<(NN + 127) / 128, 128>>>(prot, Wf0, bf0, Wf1, bf1, y, out, out_size);
}

// round 13
// speedup vs baseline: 1.1006x; 1.1006x over previous
#include <cuda_runtime.h>
#include <cuda_fp16.h>
#include <mma.h>
#include <cstdint>

using namespace nvcuda;

#define NN 50000
#define NE 800000
#define CAP 96   // max in-degree bucket capacity (Poisson(16): P(deg>=96) ~ 1e-40)

// ---------------- scratch (static device allocations; no cudaMalloc) ----------------
__device__ int   g_cnt[NN];
__device__ __align__(16) int g_colsrc[(size_t)NN * CAP];
__device__ float g_dinv[NN];
__device__ __align__(16) __half g_w16[128 * 64 + 64 * 64];  // fp16 W2|W3
__device__ __align__(16) __half g_u[(size_t)NN * 128];  // pre-agg messages, PRESCALED by dinv[src]
__device__ __align__(16) __half g_h[(size_t)NN * 128];  // post-agg activations (fp16)

// ---------------- helpers ----------------
__device__ __forceinline__ uint32_t smem_u32(const void* p) {
    uint32_t a;
    asm("{ .reg .u64 t; cvta.to.shared.u64 t, %1; cvt.u32.u64 %0, t; }" : "=r"(a) : "l"(p));
    return a;
}
__device__ __forceinline__ void cpa16(uint32_t dst, const void* src, int srcsz) {
    asm volatile("cp.async.ca.shared.global [%0], [%1], 16, %2;"
                 :: "r"(dst), "l"(src), "r"(srcsz));
}
#define CP_COMMIT() asm volatile("cp.async.commit_group;")
#define CP_WAIT(n)  asm volatile("cp.async.wait_group %0;" :: "n"(n))

// ---------------- bucket build: count + place in one edge pass ----------------
__global__ void k_place(const int* __restrict__ ei) {
    int e = blockIdx.x * blockDim.x + threadIdx.x;
    if (e < NE) {
        int s = ei[e];
        int d = ei[NE + e];
        int pos = atomicAdd(&g_cnt[d], 1);
        if (pos < CAP) g_colsrc[(size_t)d * CAP + pos] = s;
    }
}

__global__ void k_dinv() {
    int i = blockIdx.x * blockDim.x + threadIdx.x;
    if (i < NN) g_dinv[i] = rsqrtf((float)(g_cnt[i] + 1));  // +1 self loop
}

__global__ void k_wconv23(const float* __restrict__ W2, const float* __restrict__ W3) {
    int i = blockIdx.x * blockDim.x + threadIdx.x;
    const int N2 = 128 * 64, N3 = 64 * 64;
    if (i < N2) g_w16[i] = __float2half_rn(W2[i]);
    else if (i < N2 + N3) g_w16[i] = __float2half_rn(W3[i - N2]);
}

// scale U1 rows by dinv[row] (layer 1 only; layers 2/3 scale in GEMM epilogue)
__global__ void k_scale128() {
    int i = blockIdx.x * blockDim.x + threadIdx.x;  // one uint4 = 8 halves
    if (i < NN * 16) {
        int row = i >> 4;
        float dd = g_dinv[row];
        uint4 v = ((const uint4*)g_u)[i];
        uint32_t* p = (uint32_t*)&v;
        #pragma unroll
        for (int j = 0; j < 4; j++) {
            float2 f = __half22float2(*(__half2*)&p[j]);
            __half2 h = __floats2half2_rn(f.x * dd, f.y * dd);
            p[j] = *(uint32_t*)&h;
        }
        ((uint4*)g_u)[i] = v;
    }
}

// ---------------- layer-1 GEMM: register-prefetch pipeline (fp32 A) ----------------
template <int FIN, int FOUT>
__global__ void __launch_bounds__(256) k_gemm1(const float* __restrict__ Af32,
                                               const float* __restrict__ W) {
    __shared__ __align__(16) __half As[128][40];
    __shared__ __align__(16) __half Bs[32][FOUT + 8];
    __shared__ __align__(16) float  Cs[8][16][20];

    constexpr int NBI = FOUT / 64;

    int tid = threadIdx.x, wid = tid >> 5, lane = tid & 31;
    int row0 = blockIdx.x * 128;

    int ar = tid >> 1, ac0 = (tid & 1) * 16;
    int gr = row0 + ar;

    wmma::fragment<wmma::accumulator, 16, 16, 16, float> acc[FOUT / 16];
    #pragma unroll
    for (int j = 0; j < FOUT / 16; j++) wmma::fill_fragment(acc[j], 0.0f);

    float4 pa_f[4];
    float4 pb[NBI][2];

    auto loadA = [&](int k0) {
        if (gr < NN) {
            const float* src = Af32 + (size_t)gr * FIN + k0 + ac0;
            pa_f[0] = *(const float4*)(src + 0);
            pa_f[1] = *(const float4*)(src + 4);
            pa_f[2] = *(const float4*)(src + 8);
            pa_f[3] = *(const float4*)(src + 12);
        } else {
            pa_f[0] = pa_f[1] = pa_f[2] = pa_f[3] = make_float4(0, 0, 0, 0);
        }
    };
    auto loadB = [&](int k0) {
        #pragma unroll
        for (int it = 0; it < NBI; it++) {
            int idx = tid + it * 256;
            int r = idx / (FOUT / 8);
            int cb = (idx % (FOUT / 8)) * 8;
            const float* src = W + (size_t)(k0 + r) * FOUT + cb;
            pb[it][0] = *(const float4*)(src + 0);
            pb[it][1] = *(const float4*)(src + 4);
        }
    };
    auto storeA = [&]() {
        __half2 h0 = __floats2half2_rn(pa_f[0].x, pa_f[0].y), h1 = __floats2half2_rn(pa_f[0].z, pa_f[0].w);
        __half2 h2 = __floats2half2_rn(pa_f[1].x, pa_f[1].y), h3 = __floats2half2_rn(pa_f[1].z, pa_f[1].w);
        __half2 h4 = __floats2half2_rn(pa_f[2].x, pa_f[2].y), h5 = __floats2half2_rn(pa_f[2].z, pa_f[2].w);
        __half2 h6 = __floats2half2_rn(pa_f[3].x, pa_f[3].y), h7 = __floats2half2_rn(pa_f[3].z, pa_f[3].w);
        *(uint4*)&As[ar][ac0] =
            make_uint4(*(uint32_t*)&h0, *(uint32_t*)&h1, *(uint32_t*)&h2, *(uint32_t*)&h3);
        *(uint4*)&As[ar][ac0 + 8] =
            make_uint4(*(uint32_t*)&h4, *(uint32_t*)&h5, *(uint32_t*)&h6, *(uint32_t*)&h7);
    };
    auto storeB = [&]() {
        #pragma unroll
        for (int it = 0; it < NBI; it++) {
            int idx = tid + it * 256;
            int r = idx / (FOUT / 8);
            int cb = (idx % (FOUT / 8)) * 8;
            __half2 h0 = __floats2half2_rn(pb[it][0].x, pb[it][0].y);
            __half2 h1 = __floats2half2_rn(pb[it][0].z, pb[it][0].w);
            __half2 h2 = __floats2half2_rn(pb[it][1].x, pb[it][1].y);
            __half2 h3 = __floats2half2_rn(pb[it][1].z, pb[it][1].w);
            *(uint4*)&Bs[r][cb] =
                make_uint4(*(uint32_t*)&h0, *(uint32_t*)&h1, *(uint32_t*)&h2, *(uint32_t*)&h3);
        }
    };

    loadA(0);
    loadB(0);

    #pragma unroll
    for (int k0 = 0; k0 < FIN; k0 += 32) {
        storeA();
        storeB();
        __syncthreads();
        if (k0 + 32 < FIN) {
            loadA(k0 + 32);
            loadB(k0 + 32);
        }
        #pragma unroll
        for (int kk = 0; kk < 32; kk += 16) {
            wmma::fragment<wmma::matrix_a, 16, 16, 16, __half, wmma::row_major> af;
            wmma::load_matrix_sync(af, &As[wid * 16][kk], 40);
            #pragma unroll
            for (int j = 0; j < FOUT / 16; j++) {
                wmma::fragment<wmma::matrix_b, 16, 16, 16, __half, wmma::row_major> bf;
                wmma::load_matrix_sync(bf, &Bs[kk][j * 16], FOUT + 8);
                wmma::mma_sync(acc[j], af, bf, acc[j]);
            }
        }
        __syncthreads();
    }

    #pragma unroll
    for (int j = 0; j < FOUT / 16; j++) {
        wmma::store_matrix_sync(&Cs[wid][0][0], acc[j], 20, wmma::mem_row_major);
        __syncwarp();
        int r = lane >> 1, c0 = (lane & 1) * 8;
        int grr = row0 + wid * 16 + r;
        if (grr < NN) {
            const float* s = &Cs[wid][r][c0];
            __half2 h0 = __floats2half2_rn(s[0], s[1]);
            __half2 h1 = __floats2half2_rn(s[2], s[3]);
            __half2 h2 = __floats2half2_rn(s[4], s[5]);
            __half2 h3 = __floats2half2_rn(s[6], s[7]);
            *(uint4*)(g_u + (size_t)grr * FOUT + j * 16 + c0) =
                make_uint4(*(uint32_t*)&h0, *(uint32_t*)&h1, *(uint32_t*)&h2, *(uint32_t*)&h3);
        }
        __syncwarp();
    }
}

// ---------------- layers 2/3: cp.async double-buffered GEMM (fp16 A=g_h, fp16 W) ----------------
// U = (g_h @ Wh) * dinv[row]
template <int FIN, int FOUT>
__global__ void __launch_bounds__(256, 2) k_gemm_ca(const __half* __restrict__ Wh) {
    __shared__ __align__(16) __half As[2][128][40];
    __shared__ __align__(16) __half Bs[2][32][FOUT + 8];
    __shared__ __align__(16) float  Cs[8][16][20];

    constexpr int NBI = FOUT / 64;

    int tid = threadIdx.x, wid = tid >> 5, lane = tid & 31;
    int row0 = blockIdx.x * 128;

    int ar = tid >> 1, ac0 = (tid & 1) * 16;
    int asz = (row0 + ar < NN) ? 16 : 0;  // zfill OOB rows
    const __half* arow = g_h + (size_t)(row0 + ar) * FIN + ac0;

    auto loadStage = [&](int k0, int st) {
        uint32_t ad = smem_u32(&As[st][ar][ac0]);
        cpa16(ad,      arow + k0,     asz);
        cpa16(ad + 16, arow + k0 + 8, asz);
        #pragma unroll
        for (int it = 0; it < NBI; it++) {
            int chunk = tid + it * 256;
            int k = chunk / (FOUT / 8);
            int n8 = (chunk % (FOUT / 8)) * 8;
            cpa16(smem_u32(&Bs[st][k][n8]), Wh + (size_t)(k0 + k) * FOUT + n8, 16);
        }
    };

    wmma::fragment<wmma::accumulator, 16, 16, 16, float> acc[FOUT / 16];
    #pragma unroll
    for (int j = 0; j < FOUT / 16; j++) wmma::fill_fragment(acc[j], 0.0f);

    loadStage(0, 0);
    CP_COMMIT();

    int st = 0;
    #pragma unroll
    for (int k0 = 0; k0 < FIN; k0 += 32, st ^= 1) {
        if (k0 + 32 < FIN) {
            loadStage(k0 + 32, st ^ 1);
            CP_COMMIT();
            CP_WAIT(1);
        } else {
            CP_WAIT(0);
        }
        __syncthreads();
        #pragma unroll
        for (int kk = 0; kk < 32; kk += 16) {
            wmma::fragment<wmma::matrix_a, 16, 16, 16, __half, wmma::row_major> af;
            wmma::load_matrix_sync(af, &As[st][wid * 16][kk], 40);
            #pragma unroll
            for (int j = 0; j < FOUT / 16; j++) {
                wmma::fragment<wmma::matrix_b, 16, 16, 16, __half, wmma::row_major> bf;
                wmma::load_matrix_sync(bf, &Bs[st][kk][j * 16], FOUT + 8);
                wmma::mma_sync(acc[j], af, bf, acc[j]);
            }
        }
        __syncthreads();
    }

    #pragma unroll
    for (int j = 0; j < FOUT / 16; j++) {
        wmma::store_matrix_sync(&Cs[wid][0][0], acc[j], 20, wmma::mem_row_major);
        __syncwarp();
        int r = lane >> 1, c0 = (lane & 1) * 8;
        int grr = row0 + wid * 16 + r;
        if (grr < NN) {
            float dd = g_dinv[grr];
            const float* s = &Cs[wid][r][c0];
            __half2 h0 = __floats2half2_rn(s[0] * dd, s[1] * dd);
            __half2 h1 = __floats2half2_rn(s[2] * dd, s[3] * dd);
            __half2 h2 = __floats2half2_rn(s[4] * dd, s[5] * dd);
            __half2 h3 = __floats2half2_rn(s[6] * dd, s[7] * dd);
            *(uint4*)(g_u + (size_t)grr * FOUT + j * 16 + c0) =
                make_uint4(*(uint32_t*)&h0, *(uint32_t*)&h1, *(uint32_t*)&h2, *(uint32_t*)&h3);
        }
        __syncwarp();
    }
}

// ---------------- bucket gather aggregation: half2 accumulate, fp32 finish ----------------
__global__ void k_agg128(const float* __restrict__ bias) {
    int w = (blockIdx.x * blockDim.x + threadIdx.x) >> 5;
    int lane = threadIdx.x & 31;
    if (w >= NN) return;
    const uint2* Uv = (const uint2*)g_u;
    uint2 sv = Uv[(w << 5) + lane];
    __half2 a0 = *(__half2*)&sv.x, a1 = *(__half2*)&sv.y;
    int deg = g_cnt[w]; if (deg > CAP) deg = CAP;
    const int4* row4 = (const int4*)(g_colsrc + w * CAP);
    int e = 0;
    for (; e + 4 <= deg; e += 4) {
        int4 s = row4[e >> 2];
        uint2 v0 = Uv[(s.x << 5) + lane];
        uint2 v1 = Uv[(s.y << 5) + lane];
        uint2 v2 = Uv[(s.z << 5) + lane];
        uint2 v3 = Uv[(s.w << 5) + lane];
        a0 = __hadd2(a0, *(__half2*)&v0.x); a1 = __hadd2(a1, *(__half2*)&v0.y);
        a0 = __hadd2(a0, *(__half2*)&v1.x); a1 = __hadd2(a1, *(__half2*)&v1.y);
        a0 = __hadd2(a0, *(__half2*)&v2.x); a1 = __hadd2(a1, *(__half2*)&v2.y);
        a0 = __hadd2(a0, *(__half2*)&v3.x); a1 = __hadd2(a1, *(__half2*)&v3.y);
    }
    for (; e < deg; e++) {
        int s = g_colsrc[w * CAP + e];
        uint2 v = Uv[(s << 5) + lane];
        a0 = __hadd2(a0, *(__half2*)&v.x); a1 = __hadd2(a1, *(__half2*)&v.y);
    }
    float dd = g_dinv[w];
    float2 f0 = __half22float2(a0), f1 = __half22float2(a1);
    float4 bb = ((const float4*)bias)[lane];
    __half2 o0 = __floats2half2_rn(fmaxf(fmaf(f0.x, dd, bb.x), 0.f),
                                   fmaxf(fmaf(f0.y, dd, bb.y), 0.f));
    __half2 o1 = __floats2half2_rn(fmaxf(fmaf(f1.x, dd, bb.z), 0.f),
                                   fmaxf(fmaf(f1.y, dd, bb.w), 0.f));
    ((uint2*)g_h)[(w << 5) + lane] = make_uint2(*(uint32_t*)&o0, *(uint32_t*)&o1);
}

__global__ void k_agg64(const float* __restrict__ bias) {
    int w = (blockIdx.x * blockDim.x + threadIdx.x) >> 5;
    int lane = threadIdx.x & 31;
    if (w >= NN) return;
    const uint32_t* Uv = (const uint32_t*)g_u;
    uint32_t sv = Uv[(w << 5) + lane];
    __half2 a0 = *(__half2*)&sv;
    int deg = g_cnt[w]; if (deg > CAP) deg = CAP;
    const int4* row4 = (const int4*)(g_colsrc + w * CAP);
    int e = 0;
    for (; e + 4 <= deg; e += 4) {
        int4 s = row4[e >> 2];
        uint32_t v0 = Uv[(s.x << 5) + lane];
        uint32_t v1 = Uv[(s.y << 5) + lane];
        uint32_t v2 = Uv[(s.z << 5) + lane];
        uint32_t v3 = Uv[(s.w << 5) + lane];
        a0 = __hadd2(a0, *(__half2*)&v0);
        a0 = __hadd2(a0, *(__half2*)&v1);
        a0 = __hadd2(a0, *(__half2*)&v2);
        a0 = __hadd2(a0, *(__half2*)&v3);
    }
    for (; e < deg; e++) {
        int s = g_colsrc[w * CAP + e];
        uint32_t v = Uv[(s << 5) + lane];
        a0 = __hadd2(a0, *(__half2*)&v);
    }
    float dd = g_dinv[w];
    float2 f = __half22float2(a0);
    float2 bb = ((const float2*)bias)[lane];
    __half2 o = __floats2half2_rn(fmaxf(fmaf(f.x, dd, bb.x), 0.f),
                                  fmaxf(fmaf(f.y, dd, bb.y), 0.f));
    ((uint32_t*)g_h)[(w << 5) + lane] = *(uint32_t*)&o;
}

// ---------------- prototype-distance head + MLP + y copy ----------------
__device__ __forceinline__ float gelu_exact(float x) {
    return 0.5f * x * (1.0f + erff(x * 0.70710678118654752f));
}

__global__ void k_head(const float* __restrict__ prot,
                       const float* __restrict__ Wf0, const float* __restrict__ bf0,
                       const float* __restrict__ Wf1, const float* __restrict__ bf1,
                       const int* __restrict__ y,
                       float* __restrict__ out, int out_size) {
    __shared__ float hs[128][65];
    __shared__ float ps[16][64];
    __shared__ float pn[16];
    __shared__ float w0[16][8];
    __shared__ float b0[8];
    __shared__ float w1[8];
    __shared__ float b1s;

    int t = threadIdx.x;
    int nd0 = blockIdx.x * 128;

    for (int idx = t; idx < 128 * 64; idx += 128) {
        int r = idx >> 6, c = idx & 63;
        int node = nd0 + r;
        hs[r][c] = (node < NN) ? __half2float(g_h[(size_t)node * 64 + c]) : 0.f;
    }
    for (int idx = t; idx < 16 * 64; idx += 128)
        ps[idx >> 6][idx & 63] = prot[idx];
    if (t < 16 * 8) w0[t >> 3][t & 7] = Wf0[t];
    if (t < 8) { b0[t] = bf0[t]; w1[t] = Wf1[t]; }
    if (t == 0) b1s = bf1[0];
    __syncthreads();
    if (t < 16) {
        float s = 0.f;
        #pragma unroll
        for (int c = 0; c < 64; c++) s += ps[t][c] * ps[t][c];
        pn[t] = s;
    }
    __syncthreads();

    int node = nd0 + t;
    if (node < NN) {
        float hh = 0.f;
        #pragma unroll
        for (int c = 0; c < 64; c++) hh = fmaf(hs[t][c], hs[t][c], hh);

        float sim[16];
        #pragma unroll
        for (int k = 0; k < 16; k++) {
            float dot = 0.f;
            #pragma unroll
            for (int c = 0; c < 64; c++) dot = fmaf(hs[t][c], ps[k][c], dot);
            float d2 = fmaxf(hh + pn[k] - 2.0f * dot, 0.f);
            sim[k] = logf((d2 + 1.0f) / (d2 + 1e-4f));
        }

        float o = b1s;
        #pragma unroll
        for (int j = 0; j < 8; j++) {
            float z = b0[j];
            #pragma unroll
            for (int k = 0; k < 16; k++) z = fmaf(sim[k], w0[k][j], z);
            o = fmaf(gelu_exact(z), w1[j], o);
        }
        out[node] = 1.0f / (1.0f + expf(-o));
        if (NN + node < out_size) out[NN + node] = (float)y[node];
    }
}

// ---------------- launch: bucket build on s2 concurrent with GEMM1 ----------------
extern "C" void kernel_launch(void* const* d_in, const int* in_sizes, int n_in,
                              void* d_out, int out_size) {
    const float* x    = (const float*)d_in[0];
    const int*   ei   = (const int*)d_in[1];
    const int*   y    = (const int*)d_in[2];
    const float* W1   = (const float*)d_in[3];
    const float* b1   = (const float*)d_in[4];
    const float* W2   = (const float*)d_in[5];
    const float* b2   = (const float*)d_in[6];
    const float* W3   = (const float*)d_in[7];
    const float* b3   = (const float*)d_in[8];
    const float* prot = (const float*)d_in[9];
    const float* Wf0  = (const float*)d_in[10];
    const float* bf0  = (const float*)d_in[11];
    const float* Wf1  = (const float*)d_in[12];
    const float* bf1  = (const float*)d_in[13];
    float* out = (float*)d_out;

    static cudaStream_t s2 = nullptr;
    static cudaEvent_t evFork = nullptr, evJoin = nullptr;
    static void* cntPtr = nullptr;
    static __half* w16Ptr = nullptr;
    if (!s2) {
        cudaStreamCreateWithFlags(&s2, cudaStreamNonBlocking);
        cudaEventCreateWithFlags(&evFork, cudaEventDisableTiming);
        cudaEventCreateWithFlags(&evJoin, cudaEventDisableTiming);
        cudaGetSymbolAddress(&cntPtr, g_cnt);
        void* p;
        cudaGetSymbolAddress(&p, g_w16); w16Ptr = (__half*)p;
    }

    const int MT = (NN + 127) / 128;  // 391 M-tiles
    int aggBlocks = (NN * 32 + 255) / 256;

    // fork: bucket build + W2/W3 conversion on s2 (one edge pass, no prefix sums)
    cudaEventRecord(evFork, 0);
    cudaStreamWaitEvent(s2, evFork, 0);
    k_wconv23<<<(128 * 64 + 64 * 64 + 255) / 256, 256, 0, s2>>>(W2, W3);
    cudaMemsetAsync(cntPtr, 0, sizeof(int) * NN, s2);
    k_place<<<(NE + 255) / 256, 256, 0, s2>>>(ei);
    k_dinv<<<(NN + 255) / 256, 256, 0, s2>>>();
    cudaEventRecord(evJoin, s2);

    // concurrent: layer-1 GEMM (unscaled; dinv not ready yet)
    k_gemm1<128, 128><<<MT, 256>>>(x, W1);

    cudaStreamWaitEvent(0, evJoin, 0);  // join

    // prescale U1 by dinv[src], then agg; layers 2/3 scale in GEMM epilogue
    k_scale128<<<(NN * 16 + 255) / 256, 256>>>();
    k_agg128<<<aggBlocks, 256>>>(b1);
    k_gemm_ca<128, 64><<<MT, 256>>>(w16Ptr);
    k_agg64<<<aggBlocks, 256>>>(b2);
    k_gemm_ca<64, 64><<<MT, 256>>>(w16Ptr + 128 * 64);
    k_agg64<<<aggBlocks, 256>>>(b3);
    k_head<<<(NN + 127) / 128, 128>>>(prot, Wf0, bf0, Wf1, bf1, y, out, out_size);
}